// round 10
// baseline (speedup 1.0000x reference)
#include <cuda_runtime.h>
#include <cuda_fp16.h>
#include <cstdint>
#include <math.h>

#define BQ 512
#define II 2048
#define HH 2048
#define NELEM (BQ * HH)

#define BM 128
#define BN 256            // smem B cols = 64 real n x 4 gates
#define BK 64
#define STAGES 3
#define NITER 32          // per phase: 2048 / 64

#define A_LDS 72
#define B_LDS 264
#define A_STAGE_B (BM * A_LDS * 2)     // 18432
#define B_STAGE_B (BK * B_LDS * 2)     // 33792
#define STAGE_B   (A_STAGE_B + B_STAGE_B)
#define SMEM_BYTES (STAGES * STAGE_B)  // 156672
#define EPI_STRIDE 264                  // fp32 staging stride (128*264*4 = 135KB)

// B_h: [4096 k][8192 C] fp16, C = nblk*256 + gate*64 + n63  (n = nblk*64+n63)
__device__ __half A_h[(size_t)BQ * 4096];              // 4 MB
__device__ __half B_h[(size_t)4096 * 8192];            // 64 MB
__device__ float  g_preact[(size_t)BQ * 8192];         // 16 MB, same C layout

// ---------------------------------------------------------------------------
__device__ __forceinline__ uint32_t smem_u32(const void* p) {
    uint32_t a;
    asm("{ .reg .u64 t; cvta.to.shared.u64 t, %1; cvt.u32.u64 %0, t; }" : "=r"(a) : "l"(p));
    return a;
}
__device__ __forceinline__ void cpasync16(uint32_t dst, const void* src) {
    asm volatile("cp.async.cg.shared.global [%0], [%1], 16;" :: "r"(dst), "l"(src));
}
#define CP_COMMIT() asm volatile("cp.async.commit_group;" ::: "memory")
#define CP_WAIT(n)  asm volatile("cp.async.wait_group %0;" :: "n"(n) : "memory")

__device__ __forceinline__ uint32_t packh2(float lo, float hi) {
    uint32_t r; asm("cvt.rn.f16x2.f32 %0, %1, %2;" : "=r"(r) : "f"(hi), "f"(lo)); return r;
}
__device__ __forceinline__ void ldsm_x4(uint32_t* r, uint32_t addr) {
    asm volatile("ldmatrix.sync.aligned.m8n8.x4.shared.b16 {%0,%1,%2,%3}, [%4];"
                 : "=r"(r[0]), "=r"(r[1]), "=r"(r[2]), "=r"(r[3]) : "r"(addr));
}
__device__ __forceinline__ void ldsm_x4_t(uint32_t* r, uint32_t addr) {
    asm volatile("ldmatrix.sync.aligned.m8n8.x4.trans.shared.b16 {%0,%1,%2,%3}, [%4];"
                 : "=r"(r[0]), "=r"(r[1]), "=r"(r[2]), "=r"(r[3]) : "r"(addr));
}
__device__ __forceinline__ void mma16n8k16(float* c, const uint32_t* a,
                                           uint32_t b0, uint32_t b1) {
    asm volatile(
        "mma.sync.aligned.m16n8k16.row.col.f32.f16.f16.f32 "
        "{%0,%1,%2,%3}, {%4,%5,%6,%7}, {%8,%9}, {%0,%1,%2,%3};"
        : "+f"(c[0]), "+f"(c[1]), "+f"(c[2]), "+f"(c[3])
        : "r"(a[0]), "r"(a[1]), "r"(a[2]), "r"(a[3]), "r"(b0), "r"(b1));
}
__device__ __forceinline__ float sigf(float x) { return 1.0f / (1.0f + __expf(-x)); }

// ---------------------------------------------------------------------------
// fp32 -> fp16 converts
// ---------------------------------------------------------------------------
struct WPtrs { const float* p[8]; };   // Wi,Wf,Wg,Wc, Ui,Uf,Ug,Uc

__global__ __launch_bounds__(256) void convert_B(WPtrs wp, int blkofs) {
    const size_t i  = (size_t)(blockIdx.x + blkofs) * 256 + threadIdx.x;  // uint2 idx
    const size_t el = i * 4;
    const int k = (int)(el >> 13);
    const int C = (int)(el & 8191);
    const int gate = (C >> 6) & 3;
    const int n = ((C >> 8) << 6) | (C & 63);
    const float* src = (k < 2048)
        ? wp.p[gate]     + ((size_t)k << 11) + n
        : wp.p[4 + gate] + ((size_t)(k - 2048) << 11) + n;
    float4 v = *reinterpret_cast<const float4*>(src);
    uint2 o;
    o.x = packh2(v.x, v.y);
    o.y = packh2(v.z, v.w);
    reinterpret_cast<uint2*>(B_h)[i] = o;
}

__global__ __launch_bounds__(256) void convert_A(const float* __restrict__ X,
                                                 const float* __restrict__ S0) {
    const size_t i  = (size_t)blockIdx.x * 256 + threadIdx.x;
    const size_t el = i * 4;
    const int m = (int)(el >> 12);
    const int k = (int)(el & 4095);
    const float* src = (k < 2048) ? X  + ((size_t)m << 11) + k
                                  : S0 + ((size_t)m << 11) + (k - 2048);
    float4 v = *reinterpret_cast<const float4*>(src);
    uint2 o;
    o.x = packh2(v.x, v.y);
    o.y = packh2(v.z, v.w);
    reinterpret_cast<uint2*>(A_h)[i] = o;
}

// ---------------------------------------------------------------------------
// Phase GEMM. W-phase (UPHASE=0): preact = A[k<2048] @ B + bias.
// U-phase (UPHASE=1): acc = A[k>=2048] @ B; fused elementwise epilogue:
//   p = acc + preact; i,f,g,c~ gates; c = f*po + i*c~; st = g*tanh(c); write out.
// grid (4 Mtiles, 32 col-blocks), 256 threads.
// ---------------------------------------------------------------------------
template <bool UPHASE>
__global__ __launch_bounds__(256, 1) void gemm_phase(
    const float* __restrict__ b0, const float* __restrict__ b1,
    const float* __restrict__ b2, const float* __restrict__ b3,
    const float* __restrict__ prevoutput, float* __restrict__ out, int mode)
{
    extern __shared__ char smem[];
    const uint32_t sbase = smem_u32(smem);

    const int tid  = threadIdx.x;
    const int lane = tid & 31;
    const int warp = tid >> 5;
    const int wm   = (warp & 1) * 64;
    const int wn   = (warp >> 1) * 64;     // gate block = warp>>1

    const int m0 = blockIdx.x * BM;
    const int cb = blockIdx.y;             // col-block: real n base = cb*64
    const int kbase = UPHASE ? 2048 : 0;

    float acc[4][8][4];
    #pragma unroll
    for (int mt = 0; mt < 4; mt++)
        #pragma unroll
        for (int nt = 0; nt < 8; nt++)
            #pragma unroll
            for (int q = 0; q < 4; q++) acc[mt][nt][q] = 0.0f;

    auto load_chunk = [&](int i, int s) {
        const int kb = kbase + i * BK;
        const uint32_t aofs = sbase + (uint32_t)s * STAGE_B;
        const uint32_t bofs = aofs + A_STAGE_B;
        #pragma unroll
        for (int j = 0; j < 4; j++) {             // A: 1024 16B-chunks
            const int c   = tid + 256 * j;
            const int row = c >> 3, cin = c & 7;
            cpasync16(aofs + (uint32_t)(row * A_LDS + cin * 8) * 2,
                      A_h + ((size_t)(m0 + row) << 12) + kb + cin * 8);
        }
        #pragma unroll
        for (int j = 0; j < 8; j++) {             // B: 2048 16B-chunks
            const int c   = tid + 256 * j;
            const int row = c >> 5, cin = c & 31;
            cpasync16(bofs + (uint32_t)(row * B_LDS + cin * 8) * 2,
                      B_h + ((size_t)(kb + row) << 13) + cb * 256 + cin * 8);
        }
    };

    #pragma unroll
    for (int s = 0; s < STAGES - 1; s++) { load_chunk(s, s); CP_COMMIT(); }

    const int lr = lane & 15;
    const int lh = lane >> 4;

    for (int i = 0; i < NITER; i++) {
        CP_WAIT(STAGES - 2);
        __syncthreads();

        if (i + STAGES - 1 < NITER)
            load_chunk(i + STAGES - 1, (i + STAGES - 1) % STAGES);
        CP_COMMIT();

        const int s = i % STAGES;
        const uint32_t aofs = sbase + (uint32_t)s * STAGE_B;
        const uint32_t bofs = aofs + A_STAGE_B;

        #pragma unroll
        for (int ks = 0; ks < 4; ks++) {
            const int k = ks * 16;
            uint32_t a[4][4], b[4][4];
            #pragma unroll
            for (int mt = 0; mt < 4; mt++)
                ldsm_x4(a[mt], aofs +
                        (uint32_t)((wm + mt * 16 + lr) * A_LDS + k + lh * 8) * 2);
            #pragma unroll
            for (int p = 0; p < 4; p++)
                ldsm_x4_t(b[p], bofs +
                          (uint32_t)((k + lr) * B_LDS + wn + p * 16 + lh * 8) * 2);
            #pragma unroll
            for (int mt = 0; mt < 4; mt++)
                #pragma unroll
                for (int p = 0; p < 4; p++) {
                    mma16n8k16(acc[mt][2 * p + 0], a[mt], b[p][0], b[p][1]);
                    mma16n8k16(acc[mt][2 * p + 1], a[mt], b[p][2], b[p][3]);
                }
        }
        __syncthreads();
    }

    if (!UPHASE) {
        // ---- W-phase epilogue: preact = acc + bias ----
        const int gate = warp >> 1;
        const float* bias = (gate == 0) ? b0 : (gate == 1) ? b1 : (gate == 2) ? b2 : b3;
        #pragma unroll
        for (int mt = 0; mt < 4; mt++) {
            const int r0 = m0 + wm + mt * 16 + (lane >> 2);
            #pragma unroll
            for (int nt = 0; nt < 8; nt++) {
                const int colL = wn + nt * 8 + (lane & 3) * 2;
                const int nrl  = cb * 64 + (colL & 63);
                const float bx = __ldg(&bias[nrl]);
                const float by = __ldg(&bias[nrl + 1]);
                float2 v0 = make_float2(acc[mt][nt][0] + bx, acc[mt][nt][1] + by);
                float2 v1 = make_float2(acc[mt][nt][2] + bx, acc[mt][nt][3] + by);
                float* pp = g_preact + (size_t)r0 * 8192 + cb * 256 + colL;
                *reinterpret_cast<float2*>(pp) = v0;
                *reinterpret_cast<float2*>(pp + 8 * 8192) = v1;
            }
        }
    } else {
        // ---- U-phase epilogue: stage acc to smem, then fused LSTM elementwise ----
        CP_WAIT(0);
        __syncthreads();
        float* sm = reinterpret_cast<float*>(smem);   // [128][EPI_STRIDE]
        #pragma unroll
        for (int mt = 0; mt < 4; mt++) {
            const int r = wm + mt * 16 + (lane >> 2);
            #pragma unroll
            for (int nt = 0; nt < 8; nt++) {
                const int colL = wn + nt * 8 + (lane & 3) * 2;
                *reinterpret_cast<float2*>(&sm[r * EPI_STRIDE + colL]) =
                    make_float2(acc[mt][nt][0], acc[mt][nt][1]);
                *reinterpret_cast<float2*>(&sm[(r + 8) * EPI_STRIDE + colL]) =
                    make_float2(acc[mt][nt][2], acc[mt][nt][3]);
            }
        }
        __syncthreads();

        const int n63 = tid & 63;
        const int mg  = tid >> 6;
        const int n   = cb * 64 + n63;
        #pragma unroll 4
        for (int j = 0; j < 32; j++) {
            const int ml = mg * 32 + j;
            const int gm = m0 + ml;
            const float* pre = g_preact + (size_t)gm * 8192 + cb * 256 + n63;
            float p0 = sm[ml * EPI_STRIDE + n63]       + pre[0];
            float p1 = sm[ml * EPI_STRIDE + 64 + n63]  + pre[64];
            float p2 = sm[ml * EPI_STRIDE + 128 + n63] + pre[128];
            float p3 = sm[ml * EPI_STRIDE + 192 + n63] + pre[192];
            const float po = prevoutput[(size_t)gm * 2048 + n];
            const float gi = sigf(p0), gf = sigf(p1), gg = sigf(p2);
            const float gc = tanhf(p3);
            const float c  = gf * po + gi * gc;
            const float st = gg * tanhf(c);
            const size_t idx = (size_t)gm * 2048 + n;
            if (mode == 0) {
                out[idx] = c;
            } else if (mode == 1) {
                out[idx] = st; out[NELEM + idx] = c;
            } else {
                out[idx] = c; out[NELEM + idx] = st; out[2 * NELEM + idx] = c;
            }
        }
    }
}

// ---------------------------------------------------------------------------
extern "C" void kernel_launch(void* const* d_in, const int* in_sizes, int n_in,
                              void* d_out, int out_size)
{
    const float* X      = (const float*)d_in[0];
    const float* states = (const float*)d_in[1];
    const float* S0 = states;
    const float* S1 = states + NELEM;

    static cudaStream_t s2 = nullptr;
    static cudaEvent_t  e0 = nullptr, e1 = nullptr;
    static bool init_done = false;
    if (!init_done) {
        cudaFuncSetAttribute(gemm_phase<false>,
                             cudaFuncAttributeMaxDynamicSharedMemorySize, SMEM_BYTES);
        cudaFuncSetAttribute(gemm_phase<true>,
                             cudaFuncAttributeMaxDynamicSharedMemorySize, SMEM_BYTES);
        cudaStreamCreateWithFlags(&s2, cudaStreamNonBlocking);
        cudaEventCreateWithFlags(&e0, cudaEventDisableTiming);
        cudaEventCreateWithFlags(&e1, cudaEventDisableTiming);
        init_done = true;
    }

    WPtrs wp;
    wp.p[0] = (const float*)d_in[2];   // Wi
    wp.p[1] = (const float*)d_in[5];   // Wf
    wp.p[2] = (const float*)d_in[8];   // Wg
    wp.p[3] = (const float*)d_in[11];  // Wc
    wp.p[4] = (const float*)d_in[3];   // Ui
    wp.p[5] = (const float*)d_in[6];   // Uf
    wp.p[6] = (const float*)d_in[9];   // Ug
    wp.p[7] = (const float*)d_in[12];  // Uc
    const float* b0 = (const float*)d_in[4];
    const float* b1 = (const float*)d_in[7];
    const float* b2 = (const float*)d_in[10];
    const float* b3 = (const float*)d_in[13];

    int mode;
    if (out_size == NELEM)          mode = 0;
    else if (out_size == 2 * NELEM) mode = 1;
    else                            mode = 2;

    dim3 grid(BQ / BM, 32);   // 128 CTAs per phase

    // main stream: A convert + W-half B convert
    convert_A<<<2048, 256>>>(X, S0);
    convert_B<<<16384, 256>>>(wp, 0);                 // k < 2048 (W)
    cudaEventRecord(e0, (cudaStream_t)0);

    // side stream: U-half B convert, overlapped with W-phase GEMM
    cudaStreamWaitEvent(s2, e0, 0);
    convert_B<<<16384, 256, 0, s2>>>(wp, 16384);      // k >= 2048 (U)
    cudaEventRecord(e1, s2);

    // W-phase GEMM (needs only W half of B_h)
    gemm_phase<false><<<grid, 256, SMEM_BYTES>>>(b0, b1, b2, b3,
                                                 nullptr, nullptr, 0);

    // join: U-phase GEMM needs U half of B_h
    cudaStreamWaitEvent((cudaStream_t)0, e1, 0);
    gemm_phase<true><<<grid, 256, SMEM_BYTES>>>(b0, b1, b2, b3,
                                                S1, (float*)d_out, mode);
}

// round 11
// speedup vs baseline: 1.0084x; 1.0084x over previous
#include <cuda_runtime.h>
#include <cuda_fp16.h>
#include <cstdint>
#include <math.h>

#define BQ 512
#define II 2048
#define HH 2048
#define NELEM (BQ * HH)

#define BM 128
#define BN 256            // smem B cols = 64 real n x 4 gates
#define BK 64
#define STAGES 3
#define NITER 64          // full K = 4096

#define A_LDS 72
#define B_LDS 264
#define A_STAGE_B (BM * A_LDS * 2)     // 18432
#define B_STAGE_B (BK * B_LDS * 2)     // 33792
#define STAGE_B   (A_STAGE_B + B_STAGE_B)
#define SMEM_BYTES (STAGES * STAGE_B)  // 156672
#define EPI_STRIDE 264                 // fp32 staging stride (128*264*4 = 135KB)

// B_h: [4096 k][8192 C] fp16, C = nblk*256 + gate*64 + n63  (n = nblk*64 + n63)
__device__ __half A_h[(size_t)BQ * 4096];              // 4 MB
__device__ __half B_h[(size_t)4096 * 8192];            // 64 MB

// ---------------------------------------------------------------------------
__device__ __forceinline__ uint32_t smem_u32(const void* p) {
    uint32_t a;
    asm("{ .reg .u64 t; cvta.to.shared.u64 t, %1; cvt.u32.u64 %0, t; }" : "=r"(a) : "l"(p));
    return a;
}
__device__ __forceinline__ void cpasync16(uint32_t dst, const void* src) {
    asm volatile("cp.async.cg.shared.global [%0], [%1], 16;" :: "r"(dst), "l"(src));
}
#define CP_COMMIT() asm volatile("cp.async.commit_group;" ::: "memory")
#define CP_WAIT(n)  asm volatile("cp.async.wait_group %0;" :: "n"(n) : "memory")

__device__ __forceinline__ uint32_t packh2(float lo, float hi) {
    uint32_t r; asm("cvt.rn.f16x2.f32 %0, %1, %2;" : "=r"(r) : "f"(hi), "f"(lo)); return r;
}
__device__ __forceinline__ void ldsm_x4(uint32_t* r, uint32_t addr) {
    asm volatile("ldmatrix.sync.aligned.m8n8.x4.shared.b16 {%0,%1,%2,%3}, [%4];"
                 : "=r"(r[0]), "=r"(r[1]), "=r"(r[2]), "=r"(r[3]) : "r"(addr));
}
__device__ __forceinline__ void ldsm_x4_t(uint32_t* r, uint32_t addr) {
    asm volatile("ldmatrix.sync.aligned.m8n8.x4.trans.shared.b16 {%0,%1,%2,%3}, [%4];"
                 : "=r"(r[0]), "=r"(r[1]), "=r"(r[2]), "=r"(r[3]) : "r"(addr));
}
__device__ __forceinline__ void mma16n8k16(float* c, const uint32_t* a,
                                           uint32_t b0, uint32_t b1) {
    asm volatile(
        "mma.sync.aligned.m16n8k16.row.col.f32.f16.f16.f32 "
        "{%0,%1,%2,%3}, {%4,%5,%6,%7}, {%8,%9}, {%0,%1,%2,%3};"
        : "+f"(c[0]), "+f"(c[1]), "+f"(c[2]), "+f"(c[3])
        : "r"(a[0]), "r"(a[1]), "r"(a[2]), "r"(a[3]), "r"(b0), "r"(b1));
}
__device__ __forceinline__ float sigf(float x) { return 1.0f / (1.0f + __expf(-x)); }

// ---------------------------------------------------------------------------
// fp32 -> fp16 converts
// ---------------------------------------------------------------------------
struct WPtrs { const float* p[8]; };   // Wi,Wf,Wg,Wc, Ui,Uf,Ug,Uc

__global__ __launch_bounds__(256) void convert_B(WPtrs wp) {
    const size_t i  = (size_t)blockIdx.x * 256 + threadIdx.x;   // uint2 idx
    const size_t el = i * 4;
    const int k = (int)(el >> 13);
    const int C = (int)(el & 8191);
    const int gate = (C >> 6) & 3;
    const int n = ((C >> 8) << 6) | (C & 63);
    const float* src = (k < 2048)
        ? wp.p[gate]     + ((size_t)k << 11) + n
        : wp.p[4 + gate] + ((size_t)(k - 2048) << 11) + n;
    float4 v = *reinterpret_cast<const float4*>(src);
    uint2 o;
    o.x = packh2(v.x, v.y);
    o.y = packh2(v.z, v.w);
    reinterpret_cast<uint2*>(B_h)[i] = o;
}

__global__ __launch_bounds__(256) void convert_A(const float* __restrict__ X,
                                                 const float* __restrict__ S0) {
    const size_t i  = (size_t)blockIdx.x * 256 + threadIdx.x;
    const size_t el = i * 4;
    const int m = (int)(el >> 12);
    const int k = (int)(el & 4095);
    const float* src = (k < 2048) ? X  + ((size_t)m << 11) + k
                                  : S0 + ((size_t)m << 11) + (k - 2048);
    float4 v = *reinterpret_cast<const float4*>(src);
    uint2 o;
    o.x = packh2(v.x, v.y);
    o.y = packh2(v.z, v.w);
    reinterpret_cast<uint2*>(A_h)[i] = o;
}

// ---------------------------------------------------------------------------
// Full-K fused GEMM + LSTM elementwise:
//   acc[m, (gate,n)] = sum_k A_h[m,k] * B_h[k, C(gate,n)]
//   p = acc + bias[gate]; i,f,g,c~; c = f*po + i*c~; st = g*tanh(c); write out.
// grid (4 Mtiles, 32 col-blocks) = 128 CTAs, 256 threads.
// Fragments double-buffered across ks steps to keep HMMA pipe fed.
// ---------------------------------------------------------------------------
__global__ __launch_bounds__(256, 1) void gemm_fused(
    const float* __restrict__ b0, const float* __restrict__ b1,
    const float* __restrict__ b2, const float* __restrict__ b3,
    const float* __restrict__ prevoutput, float* __restrict__ out, int mode)
{
    extern __shared__ char smem[];
    const uint32_t sbase = smem_u32(smem);

    const int tid  = threadIdx.x;
    const int lane = tid & 31;
    const int warp = tid >> 5;
    const int wm   = (warp & 1) * 64;
    const int wn   = (warp >> 1) * 64;     // gate block = warp>>1

    const int m0 = blockIdx.x * BM;
    const int cb = blockIdx.y;             // real n base = cb*64

    float acc[4][8][4];
    #pragma unroll
    for (int mt = 0; mt < 4; mt++)
        #pragma unroll
        for (int nt = 0; nt < 8; nt++)
            #pragma unroll
            for (int q = 0; q < 4; q++) acc[mt][nt][q] = 0.0f;

    auto load_chunk = [&](int i, int s) {
        const int kb = i * BK;
        const uint32_t aofs = sbase + (uint32_t)s * STAGE_B;
        const uint32_t bofs = aofs + A_STAGE_B;
        #pragma unroll
        for (int j = 0; j < 4; j++) {             // A: 1024 16B-chunks
            const int c   = tid + 256 * j;
            const int row = c >> 3, cin = c & 7;
            cpasync16(aofs + (uint32_t)(row * A_LDS + cin * 8) * 2,
                      A_h + ((size_t)(m0 + row) << 12) + kb + cin * 8);
        }
        #pragma unroll
        for (int j = 0; j < 8; j++) {             // B: 2048 16B-chunks
            const int c   = tid + 256 * j;
            const int row = c >> 5, cin = c & 31;
            cpasync16(bofs + (uint32_t)(row * B_LDS + cin * 8) * 2,
                      B_h + ((size_t)(kb + row) << 13) + cb * 256 + cin * 8);
        }
    };

    #pragma unroll
    for (int s = 0; s < STAGES - 1; s++) { load_chunk(s, s); CP_COMMIT(); }

    const int lr = lane & 15;
    const int lh = lane >> 4;

    uint32_t afr[2][4][4], bfr[2][4][4];

    for (int i = 0; i < NITER; i++) {
        CP_WAIT(STAGES - 2);
        __syncthreads();

        if (i + STAGES - 1 < NITER)
            load_chunk(i + STAGES - 1, (i + STAGES - 1) % STAGES);
        CP_COMMIT();

        const int s = i % STAGES;
        const uint32_t aofs = sbase + (uint32_t)s * STAGE_B;
        const uint32_t bofs = aofs + A_STAGE_B;

        // load ks=0 fragments into buffer 0
        #pragma unroll
        for (int mt = 0; mt < 4; mt++)
            ldsm_x4(afr[0][mt], aofs +
                    (uint32_t)((wm + mt * 16 + lr) * A_LDS + lh * 8) * 2);
        #pragma unroll
        for (int p = 0; p < 4; p++)
            ldsm_x4_t(bfr[0][p], bofs +
                      (uint32_t)(lr * B_LDS + wn + p * 16 + lh * 8) * 2);

        #pragma unroll
        for (int ks = 0; ks < 4; ks++) {
            const int cur = ks & 1;
            // prefetch next ks fragments into the other buffer
            if (ks < 3) {
                const int k = (ks + 1) * 16;
                const int nxt = cur ^ 1;
                #pragma unroll
                for (int mt = 0; mt < 4; mt++)
                    ldsm_x4(afr[nxt][mt], aofs +
                            (uint32_t)((wm + mt * 16 + lr) * A_LDS + k + lh * 8) * 2);
                #pragma unroll
                for (int p = 0; p < 4; p++)
                    ldsm_x4_t(bfr[nxt][p], bofs +
                              (uint32_t)((k + lr) * B_LDS + wn + p * 16 + lh * 8) * 2);
            }
            #pragma unroll
            for (int mt = 0; mt < 4; mt++)
                #pragma unroll
                for (int p = 0; p < 4; p++) {
                    mma16n8k16(acc[mt][2 * p + 0], afr[cur][mt],
                               bfr[cur][p][0], bfr[cur][p][1]);
                    mma16n8k16(acc[mt][2 * p + 1], afr[cur][mt],
                               bfr[cur][p][2], bfr[cur][p][3]);
                }
        }
        __syncthreads();
    }

    // ---- epilogue: stage acc to smem, then fused LSTM elementwise ----
    CP_WAIT(0);
    __syncthreads();
    float* sm = reinterpret_cast<float*>(smem);   // [128][EPI_STRIDE]
    #pragma unroll
    for (int mt = 0; mt < 4; mt++) {
        const int r = wm + mt * 16 + (lane >> 2);
        #pragma unroll
        for (int nt = 0; nt < 8; nt++) {
            const int colL = wn + nt * 8 + (lane & 3) * 2;
            *reinterpret_cast<float2*>(&sm[r * EPI_STRIDE + colL]) =
                make_float2(acc[mt][nt][0], acc[mt][nt][1]);
            *reinterpret_cast<float2*>(&sm[(r + 8) * EPI_STRIDE + colL]) =
                make_float2(acc[mt][nt][2], acc[mt][nt][3]);
        }
    }
    __syncthreads();

    const int n63 = tid & 63;
    const int mg  = tid >> 6;
    const int n   = cb * 64 + n63;
    const float bi_ = __ldg(&b0[n]);
    const float bf_ = __ldg(&b1[n]);
    const float bg_ = __ldg(&b2[n]);
    const float bc_ = __ldg(&b3[n]);
    #pragma unroll 4
    for (int j = 0; j < 32; j++) {
        const int ml = mg * 32 + j;
        const int gm = m0 + ml;
        const float p0 = sm[ml * EPI_STRIDE + n63]       + bi_;
        const float p1 = sm[ml * EPI_STRIDE + 64 + n63]  + bf_;
        const float p2 = sm[ml * EPI_STRIDE + 128 + n63] + bg_;
        const float p3 = sm[ml * EPI_STRIDE + 192 + n63] + bc_;
        const float po = prevoutput[(size_t)gm * 2048 + n];
        const float gi = sigf(p0), gf = sigf(p1), gg = sigf(p2);
        const float gc = tanhf(p3);
        const float c  = gf * po + gi * gc;
        const float st = gg * tanhf(c);
        const size_t idx = (size_t)gm * 2048 + n;
        if (mode == 0) {
            out[idx] = c;
        } else if (mode == 1) {
            out[idx] = st; out[NELEM + idx] = c;
        } else {
            out[idx] = c; out[NELEM + idx] = st; out[2 * NELEM + idx] = c;
        }
    }
}

// ---------------------------------------------------------------------------
extern "C" void kernel_launch(void* const* d_in, const int* in_sizes, int n_in,
                              void* d_out, int out_size)
{
    const float* X      = (const float*)d_in[0];
    const float* states = (const float*)d_in[1];
    const float* S0 = states;
    const float* S1 = states + NELEM;

    static bool init_done = false;
    if (!init_done) {
        cudaFuncSetAttribute(gemm_fused,
                             cudaFuncAttributeMaxDynamicSharedMemorySize, SMEM_BYTES);
        init_done = true;
    }

    WPtrs wp;
    wp.p[0] = (const float*)d_in[2];   // Wi
    wp.p[1] = (const float*)d_in[5];   // Wf
    wp.p[2] = (const float*)d_in[8];   // Wg
    wp.p[3] = (const float*)d_in[11];  // Wc
    wp.p[4] = (const float*)d_in[3];   // Ui
    wp.p[5] = (const float*)d_in[6];   // Uf
    wp.p[6] = (const float*)d_in[9];   // Ug
    wp.p[7] = (const float*)d_in[12];  // Uc
    const float* b0 = (const float*)d_in[4];
    const float* b1 = (const float*)d_in[7];
    const float* b2 = (const float*)d_in[10];
    const float* b3 = (const float*)d_in[13];

    int mode;
    if (out_size == NELEM)          mode = 0;
    else if (out_size == 2 * NELEM) mode = 1;
    else                            mode = 2;

    convert_A<<<2048, 256>>>(X, S0);
    convert_B<<<32768, 256>>>(wp);

    dim3 grid(BQ / BM, 32);   // 128 CTAs
    gemm_fused<<<grid, 256, SMEM_BYTES>>>(b0, b1, b2, b3, S1, (float*)d_out, mode);
}

// round 12
// speedup vs baseline: 1.1050x; 1.0958x over previous
#include <cuda_runtime.h>
#include <cuda_fp16.h>
#include <cstdint>
#include <math.h>

#define BQ 512
#define II 2048
#define HH 2048
#define NELEM (BQ * HH)

#define BM 128
#define BN 256            // smem B cols = 64 real n x 4 gates
#define BK 64
#define STAGES 3
#define NITER 64          // full K = 4096
#define NTHREADS 512

#define A_LDS 72
#define B_LDS 264
#define A_STAGE_B (BM * A_LDS * 2)     // 18432
#define B_STAGE_B (BK * B_LDS * 2)     // 33792
#define STAGE_B   (A_STAGE_B + B_STAGE_B)
#define SMEM_BYTES (STAGES * STAGE_B)  // 156672
#define EPI_STRIDE 264                 // fp32 staging stride (128*264*4 = 135KB)

// B_h: [4096 k][8192 C] fp16, C = nblk*256 + gate*64 + n63  (n = nblk*64 + n63)
__device__ __half A_h[(size_t)BQ * 4096];              // 4 MB
__device__ __half B_h[(size_t)4096 * 8192];            // 64 MB

// ---------------------------------------------------------------------------
__device__ __forceinline__ uint32_t smem_u32(const void* p) {
    uint32_t a;
    asm("{ .reg .u64 t; cvta.to.shared.u64 t, %1; cvt.u32.u64 %0, t; }" : "=r"(a) : "l"(p));
    return a;
}
__device__ __forceinline__ void cpasync16(uint32_t dst, const void* src) {
    asm volatile("cp.async.cg.shared.global [%0], [%1], 16;" :: "r"(dst), "l"(src));
}
#define CP_COMMIT() asm volatile("cp.async.commit_group;" ::: "memory")
#define CP_WAIT(n)  asm volatile("cp.async.wait_group %0;" :: "n"(n) : "memory")

__device__ __forceinline__ uint32_t packh2(float lo, float hi) {
    uint32_t r; asm("cvt.rn.f16x2.f32 %0, %1, %2;" : "=r"(r) : "f"(hi), "f"(lo)); return r;
}
__device__ __forceinline__ void ldsm_x4(uint32_t* r, uint32_t addr) {
    asm volatile("ldmatrix.sync.aligned.m8n8.x4.shared.b16 {%0,%1,%2,%3}, [%4];"
                 : "=r"(r[0]), "=r"(r[1]), "=r"(r[2]), "=r"(r[3]) : "r"(addr));
}
__device__ __forceinline__ void ldsm_x4_t(uint32_t* r, uint32_t addr) {
    asm volatile("ldmatrix.sync.aligned.m8n8.x4.trans.shared.b16 {%0,%1,%2,%3}, [%4];"
                 : "=r"(r[0]), "=r"(r[1]), "=r"(r[2]), "=r"(r[3]) : "r"(addr));
}
__device__ __forceinline__ void mma16n8k16(float* c, const uint32_t* a,
                                           uint32_t b0, uint32_t b1) {
    asm volatile(
        "mma.sync.aligned.m16n8k16.row.col.f32.f16.f16.f32 "
        "{%0,%1,%2,%3}, {%4,%5,%6,%7}, {%8,%9}, {%0,%1,%2,%3};"
        : "+f"(c[0]), "+f"(c[1]), "+f"(c[2]), "+f"(c[3])
        : "r"(a[0]), "r"(a[1]), "r"(a[2]), "r"(a[3]), "r"(b0), "r"(b1));
}
__device__ __forceinline__ float sigf(float x) { return 1.0f / (1.0f + __expf(-x)); }

// ---------------------------------------------------------------------------
// fp32 -> fp16 converts
// ---------------------------------------------------------------------------
struct WPtrs { const float* p[8]; };   // Wi,Wf,Wg,Wc, Ui,Uf,Ug,Uc

__global__ __launch_bounds__(256) void convert_B(WPtrs wp) {
    const size_t i  = (size_t)blockIdx.x * 256 + threadIdx.x;   // uint2 idx
    const size_t el = i * 4;
    const int k = (int)(el >> 13);
    const int C = (int)(el & 8191);
    const int gate = (C >> 6) & 3;
    const int n = ((C >> 8) << 6) | (C & 63);
    const float* src = (k < 2048)
        ? wp.p[gate]     + ((size_t)k << 11) + n
        : wp.p[4 + gate] + ((size_t)(k - 2048) << 11) + n;
    float4 v = *reinterpret_cast<const float4*>(src);
    uint2 o;
    o.x = packh2(v.x, v.y);
    o.y = packh2(v.z, v.w);
    reinterpret_cast<uint2*>(B_h)[i] = o;
}

__global__ __launch_bounds__(256) void convert_A(const float* __restrict__ X,
                                                 const float* __restrict__ S0) {
    const size_t i  = (size_t)blockIdx.x * 256 + threadIdx.x;
    const size_t el = i * 4;
    const int m = (int)(el >> 12);
    const int k = (int)(el & 4095);
    const float* src = (k < 2048) ? X  + ((size_t)m << 11) + k
                                  : S0 + ((size_t)m << 11) + (k - 2048);
    float4 v = *reinterpret_cast<const float4*>(src);
    uint2 o;
    o.x = packh2(v.x, v.y);
    o.y = packh2(v.z, v.w);
    reinterpret_cast<uint2*>(A_h)[i] = o;
}

// ---------------------------------------------------------------------------
// Full-K fused GEMM + LSTM elementwise. 512 threads, 16 warps.
// Warp grid 4(M) x 4(N): warp tile 32x64 (each N-quad = one gate).
// grid (4 Mtiles, 32 col-blocks) = 128 CTAs.
// ---------------------------------------------------------------------------
__global__ __launch_bounds__(NTHREADS, 1) void gemm_fused(
    const float* __restrict__ b0, const float* __restrict__ b1,
    const float* __restrict__ b2, const float* __restrict__ b3,
    const float* __restrict__ prevoutput, float* __restrict__ out, int mode)
{
    extern __shared__ char smem[];
    const uint32_t sbase = smem_u32(smem);

    const int tid  = threadIdx.x;
    const int lane = tid & 31;
    const int warp = tid >> 5;
    const int wm   = (warp & 3) * 32;      // warp M offset
    const int wn   = (warp >> 2) * 64;     // warp N offset (gate = warp>>2)

    const int m0 = blockIdx.x * BM;
    const int cb = blockIdx.y;             // real n base = cb*64

    float acc[2][8][4];
    #pragma unroll
    for (int mt = 0; mt < 2; mt++)
        #pragma unroll
        for (int nt = 0; nt < 8; nt++)
            #pragma unroll
            for (int q = 0; q < 4; q++) acc[mt][nt][q] = 0.0f;

    auto load_chunk = [&](int i, int s) {
        const int kb = i * BK;
        const uint32_t aofs = sbase + (uint32_t)s * STAGE_B;
        const uint32_t bofs = aofs + A_STAGE_B;
        #pragma unroll
        for (int j = 0; j < 2; j++) {             // A: 1024 16B-chunks
            const int c   = tid + NTHREADS * j;
            const int row = c >> 3, cin = c & 7;
            cpasync16(aofs + (uint32_t)(row * A_LDS + cin * 8) * 2,
                      A_h + ((size_t)(m0 + row) << 12) + kb + cin * 8);
        }
        #pragma unroll
        for (int j = 0; j < 4; j++) {             // B: 2048 16B-chunks
            const int c   = tid + NTHREADS * j;
            const int row = c >> 5, cin = c & 31;
            cpasync16(bofs + (uint32_t)(row * B_LDS + cin * 8) * 2,
                      B_h + ((size_t)(kb + row) << 13) + cb * 256 + cin * 8);
        }
    };

    #pragma unroll
    for (int s = 0; s < STAGES - 1; s++) { load_chunk(s, s); CP_COMMIT(); }

    const int lr = lane & 15;
    const int lh = lane >> 4;

    for (int i = 0; i < NITER; i++) {
        CP_WAIT(STAGES - 2);
        __syncthreads();

        if (i + STAGES - 1 < NITER)
            load_chunk(i + STAGES - 1, (i + STAGES - 1) % STAGES);
        CP_COMMIT();

        const int s = i % STAGES;
        const uint32_t aofs = sbase + (uint32_t)s * STAGE_B;
        const uint32_t bofs = aofs + A_STAGE_B;

        #pragma unroll
        for (int ks = 0; ks < 4; ks++) {
            const int k = ks * 16;
            uint32_t a[2][4], b[4][4];
            #pragma unroll
            for (int mt = 0; mt < 2; mt++)
                ldsm_x4(a[mt], aofs +
                        (uint32_t)((wm + mt * 16 + lr) * A_LDS + k + lh * 8) * 2);
            #pragma unroll
            for (int p = 0; p < 4; p++)
                ldsm_x4_t(b[p], bofs +
                          (uint32_t)((k + lr) * B_LDS + wn + p * 16 + lh * 8) * 2);
            #pragma unroll
            for (int mt = 0; mt < 2; mt++)
                #pragma unroll
                for (int p = 0; p < 4; p++) {
                    mma16n8k16(acc[mt][2 * p + 0], a[mt], b[p][0], b[p][1]);
                    mma16n8k16(acc[mt][2 * p + 1], a[mt], b[p][2], b[p][3]);
                }
        }
        __syncthreads();
    }

    // ---- epilogue: stage acc to smem, then fused LSTM elementwise ----
    CP_WAIT(0);
    __syncthreads();
    float* sm = reinterpret_cast<float*>(smem);   // [128][EPI_STRIDE]
    #pragma unroll
    for (int mt = 0; mt < 2; mt++) {
        const int r = wm + mt * 16 + (lane >> 2);
        #pragma unroll
        for (int nt = 0; nt < 8; nt++) {
            const int colL = wn + nt * 8 + (lane & 3) * 2;
            *reinterpret_cast<float2*>(&sm[r * EPI_STRIDE + colL]) =
                make_float2(acc[mt][nt][0], acc[mt][nt][1]);
            *reinterpret_cast<float2*>(&sm[(r + 8) * EPI_STRIDE + colL]) =
                make_float2(acc[mt][nt][2], acc[mt][nt][3]);
        }
    }
    __syncthreads();

    const int n63 = tid & 63;
    const int mg  = tid >> 6;              // 0..7
    const int n   = cb * 64 + n63;
    const float bi_ = __ldg(&b0[n]);
    const float bf_ = __ldg(&b1[n]);
    const float bg_ = __ldg(&b2[n]);
    const float bc_ = __ldg(&b3[n]);
    #pragma unroll 4
    for (int j = 0; j < 16; j++) {
        const int ml = mg * 16 + j;
        const int gm = m0 + ml;
        const float p0 = sm[ml * EPI_STRIDE + n63]       + bi_;
        const float p1 = sm[ml * EPI_STRIDE + 64 + n63]  + bf_;
        const float p2 = sm[ml * EPI_STRIDE + 128 + n63] + bg_;
        const float p3 = sm[ml * EPI_STRIDE + 192 + n63] + bc_;
        const float po = prevoutput[(size_t)gm * 2048 + n];
        const float gi = sigf(p0), gf = sigf(p1), gg = sigf(p2);
        const float gc = tanhf(p3);
        const float c  = gf * po + gi * gc;
        const float st = gg * tanhf(c);
        const size_t idx = (size_t)gm * 2048 + n;
        if (mode == 0) {
            out[idx] = c;
        } else if (mode == 1) {
            out[idx] = st; out[NELEM + idx] = c;
        } else {
            out[idx] = c; out[NELEM + idx] = st; out[2 * NELEM + idx] = c;
        }
    }
}

// ---------------------------------------------------------------------------
extern "C" void kernel_launch(void* const* d_in, const int* in_sizes, int n_in,
                              void* d_out, int out_size)
{
    const float* X      = (const float*)d_in[0];
    const float* states = (const float*)d_in[1];
    const float* S0 = states;
    const float* S1 = states + NELEM;

    static bool init_done = false;
    if (!init_done) {
        cudaFuncSetAttribute(gemm_fused,
                             cudaFuncAttributeMaxDynamicSharedMemorySize, SMEM_BYTES);
        init_done = true;
    }

    WPtrs wp;
    wp.p[0] = (const float*)d_in[2];   // Wi
    wp.p[1] = (const float*)d_in[5];   // Wf
    wp.p[2] = (const float*)d_in[8];   // Wg
    wp.p[3] = (const float*)d_in[11];  // Wc
    wp.p[4] = (const float*)d_in[3];   // Ui
    wp.p[5] = (const float*)d_in[6];   // Uf
    wp.p[6] = (const float*)d_in[9];   // Ug
    wp.p[7] = (const float*)d_in[12];  // Uc
    const float* b0 = (const float*)d_in[4];
    const float* b1 = (const float*)d_in[7];
    const float* b2 = (const float*)d_in[10];
    const float* b3 = (const float*)d_in[13];

    int mode;
    if (out_size == NELEM)          mode = 0;
    else if (out_size == 2 * NELEM) mode = 1;
    else                            mode = 2;

    convert_A<<<2048, 256>>>(X, S0);
    convert_B<<<32768, 256>>>(wp);

    dim3 grid(BQ / BM, 32);   // 128 CTAs
    gemm_fused<<<grid, NTHREADS, SMEM_BYTES>>>(b0, b1, b2, b3, S1, (float*)d_out, mode);
}

// round 13
// speedup vs baseline: 1.1752x; 1.0635x over previous
#include <cuda_runtime.h>
#include <cuda_fp16.h>
#include <cstdint>
#include <math.h>

#define BQ 512
#define II 2048
#define HH 2048
#define NELEM (BQ * HH)

#define BM 128
#define BN 256            // smem B cols = 64 real n x 4 gates
#define BK 64
#define STAGES 3
#define NITER 64          // full K = 4096
#define NTHREADS 512

#define A_LDS 72
#define B_LDS 264
#define A_STAGE_B (BM * A_LDS * 2)     // 18432
#define B_STAGE_B (BK * B_LDS * 2)     // 33792
#define STAGE_B   (A_STAGE_B + B_STAGE_B)
#define SMEM_BYTES (STAGES * STAGE_B)  // 156672
#define EPI_STRIDE 264                 // fp32 staging stride (128*264*4 = 135KB)

// B_h: [4096 k][8192 C] fp16, C = nblk*256 + gate*64 + n63  (n = nblk*64 + n63)
__device__ __half A_h[(size_t)BQ * 4096];              // 4 MB
__device__ __half B_h[(size_t)4096 * 8192];            // 64 MB

// ---------------------------------------------------------------------------
__device__ __forceinline__ uint32_t smem_u32(const void* p) {
    uint32_t a;
    asm("{ .reg .u64 t; cvta.to.shared.u64 t, %1; cvt.u32.u64 %0, t; }" : "=r"(a) : "l"(p));
    return a;
}
__device__ __forceinline__ void cpasync16(uint32_t dst, const void* src) {
    asm volatile("cp.async.cg.shared.global [%0], [%1], 16;" :: "r"(dst), "l"(src));
}
#define CP_COMMIT() asm volatile("cp.async.commit_group;" ::: "memory")
#define CP_WAIT(n)  asm volatile("cp.async.wait_group %0;" :: "n"(n) : "memory")

__device__ __forceinline__ uint32_t packh2(float lo, float hi) {
    uint32_t r; asm("cvt.rn.f16x2.f32 %0, %1, %2;" : "=r"(r) : "f"(hi), "f"(lo)); return r;
}
__device__ __forceinline__ void ldsm_x4(uint32_t* r, uint32_t addr) {
    asm volatile("ldmatrix.sync.aligned.m8n8.x4.shared.b16 {%0,%1,%2,%3}, [%4];"
                 : "=r"(r[0]), "=r"(r[1]), "=r"(r[2]), "=r"(r[3]) : "r"(addr));
}
__device__ __forceinline__ void ldsm_x4_t(uint32_t* r, uint32_t addr) {
    asm volatile("ldmatrix.sync.aligned.m8n8.x4.trans.shared.b16 {%0,%1,%2,%3}, [%4];"
                 : "=r"(r[0]), "=r"(r[1]), "=r"(r[2]), "=r"(r[3]) : "r"(addr));
}
__device__ __forceinline__ void mma16n8k16(float* c, const uint32_t* a,
                                           uint32_t b0, uint32_t b1) {
    asm volatile(
        "mma.sync.aligned.m16n8k16.row.col.f32.f16.f16.f32 "
        "{%0,%1,%2,%3}, {%4,%5,%6,%7}, {%8,%9}, {%0,%1,%2,%3};"
        : "+f"(c[0]), "+f"(c[1]), "+f"(c[2]), "+f"(c[3])
        : "r"(a[0]), "r"(a[1]), "r"(a[2]), "r"(a[3]), "r"(b0), "r"(b1));
}
__device__ __forceinline__ float sigf(float x) { return 1.0f / (1.0f + __expf(-x)); }

// ---------------------------------------------------------------------------
// fp32 -> fp16 converts, MLP=8 per thread (32 consecutive halfs each)
// ---------------------------------------------------------------------------
struct WPtrs { const float* p[8]; };   // Wi,Wf,Wg,Wc, Ui,Uf,Ug,Uc

// 4096 blocks x 256 thr: each thread converts 32 consecutive halfs of B_h.
// The 32-half span stays inside one (k, gate) block: C0 is 32-aligned and
// gate blocks are 64 wide.
__global__ __launch_bounds__(256) void convert_B(WPtrs wp) {
    const uint32_t gid = blockIdx.x * 256 + threadIdx.x;
    const size_t el0 = (size_t)gid * 32;              // half index
    const int k  = (int)(el0 >> 13);
    const int C0 = (int)(el0 & 8191);
    const int gate = (C0 >> 6) & 3;
    const int n = ((C0 >> 8) << 6) | (C0 & 63);
    const float* base = (k < 2048)
        ? wp.p[gate]     + ((size_t)k << 11) + n
        : wp.p[4 + gate] + ((size_t)(k - 2048) << 11) + n;

    float4 v[8];
    #pragma unroll
    for (int j = 0; j < 8; j++)
        v[j] = reinterpret_cast<const float4*>(base)[j];

    uint2* dst = reinterpret_cast<uint2*>(B_h) + (size_t)gid * 8;
    #pragma unroll
    for (int j = 0; j < 8; j++) {
        uint2 o;
        o.x = packh2(v[j].x, v[j].y);
        o.y = packh2(v[j].z, v[j].w);
        dst[j] = o;
    }
}

// 256 blocks x 256 thr: each thread converts 32 consecutive halfs of A_h.
// Span stays inside X or S0 half (k0 32-aligned, boundary at 2048).
__global__ __launch_bounds__(256) void convert_A(const float* __restrict__ X,
                                                 const float* __restrict__ S0) {
    const uint32_t gid = blockIdx.x * 256 + threadIdx.x;
    const size_t el0 = (size_t)gid * 32;
    const int m  = (int)(el0 >> 12);
    const int k0 = (int)(el0 & 4095);
    const float* base = (k0 < 2048) ? X  + ((size_t)m << 11) + k0
                                    : S0 + ((size_t)m << 11) + (k0 - 2048);
    float4 v[8];
    #pragma unroll
    for (int j = 0; j < 8; j++)
        v[j] = reinterpret_cast<const float4*>(base)[j];

    uint2* dst = reinterpret_cast<uint2*>(A_h) + (size_t)gid * 8;
    #pragma unroll
    for (int j = 0; j < 8; j++) {
        uint2 o;
        o.x = packh2(v[j].x, v[j].y);
        o.y = packh2(v[j].z, v[j].w);
        dst[j] = o;
    }
}

// ---------------------------------------------------------------------------
// Full-K fused GEMM + LSTM elementwise. 512 threads, 16 warps.
// Warp grid 4(M) x 4(N): warp tile 32x64 (each N-quad = one gate).
// grid (4 Mtiles, 32 col-blocks) = 128 CTAs.
// ---------------------------------------------------------------------------
__global__ __launch_bounds__(NTHREADS, 1) void gemm_fused(
    const float* __restrict__ b0, const float* __restrict__ b1,
    const float* __restrict__ b2, const float* __restrict__ b3,
    const float* __restrict__ prevoutput, float* __restrict__ out, int mode)
{
    extern __shared__ char smem[];
    const uint32_t sbase = smem_u32(smem);

    const int tid  = threadIdx.x;
    const int lane = tid & 31;
    const int warp = tid >> 5;
    const int wm   = (warp & 3) * 32;      // warp M offset
    const int wn   = (warp >> 2) * 64;     // warp N offset (gate = warp>>2)

    const int m0 = blockIdx.x * BM;
    const int cb = blockIdx.y;             // real n base = cb*64

    float acc[2][8][4];
    #pragma unroll
    for (int mt = 0; mt < 2; mt++)
        #pragma unroll
        for (int nt = 0; nt < 8; nt++)
            #pragma unroll
            for (int q = 0; q < 4; q++) acc[mt][nt][q] = 0.0f;

    auto load_chunk = [&](int i, int s) {
        const int kb = i * BK;
        const uint32_t aofs = sbase + (uint32_t)s * STAGE_B;
        const uint32_t bofs = aofs + A_STAGE_B;
        #pragma unroll
        for (int j = 0; j < 2; j++) {             // A: 1024 16B-chunks
            const int c   = tid + NTHREADS * j;
            const int row = c >> 3, cin = c & 7;
            cpasync16(aofs + (uint32_t)(row * A_LDS + cin * 8) * 2,
                      A_h + ((size_t)(m0 + row) << 12) + kb + cin * 8);
        }
        #pragma unroll
        for (int j = 0; j < 4; j++) {             // B: 2048 16B-chunks
            const int c   = tid + NTHREADS * j;
            const int row = c >> 5, cin = c & 31;
            cpasync16(bofs + (uint32_t)(row * B_LDS + cin * 8) * 2,
                      B_h + ((size_t)(kb + row) << 13) + cb * 256 + cin * 8);
        }
    };

    #pragma unroll
    for (int s = 0; s < STAGES - 1; s++) { load_chunk(s, s); CP_COMMIT(); }

    const int lr = lane & 15;
    const int lh = lane >> 4;

    for (int i = 0; i < NITER; i++) {
        CP_WAIT(STAGES - 2);
        __syncthreads();

        if (i + STAGES - 1 < NITER)
            load_chunk(i + STAGES - 1, (i + STAGES - 1) % STAGES);
        CP_COMMIT();

        const int s = i % STAGES;
        const uint32_t aofs = sbase + (uint32_t)s * STAGE_B;
        const uint32_t bofs = aofs + A_STAGE_B;

        #pragma unroll
        for (int ks = 0; ks < 4; ks++) {
            const int k = ks * 16;
            uint32_t a[2][4], b[4][4];
            #pragma unroll
            for (int mt = 0; mt < 2; mt++)
                ldsm_x4(a[mt], aofs +
                        (uint32_t)((wm + mt * 16 + lr) * A_LDS + k + lh * 8) * 2);
            #pragma unroll
            for (int p = 0; p < 4; p++)
                ldsm_x4_t(b[p], bofs +
                          (uint32_t)((k + lr) * B_LDS + wn + p * 16 + lh * 8) * 2);
            #pragma unroll
            for (int mt = 0; mt < 2; mt++)
                #pragma unroll
                for (int p = 0; p < 4; p++) {
                    mma16n8k16(acc[mt][2 * p + 0], a[mt], b[p][0], b[p][1]);
                    mma16n8k16(acc[mt][2 * p + 1], a[mt], b[p][2], b[p][3]);
                }
        }
        __syncthreads();
    }

    // ---- epilogue: stage acc to smem, then fused LSTM elementwise ----
    CP_WAIT(0);
    __syncthreads();
    float* sm = reinterpret_cast<float*>(smem);   // [128][EPI_STRIDE]
    #pragma unroll
    for (int mt = 0; mt < 2; mt++) {
        const int r = wm + mt * 16 + (lane >> 2);
        #pragma unroll
        for (int nt = 0; nt < 8; nt++) {
            const int colL = wn + nt * 8 + (lane & 3) * 2;
            *reinterpret_cast<float2*>(&sm[r * EPI_STRIDE + colL]) =
                make_float2(acc[mt][nt][0], acc[mt][nt][1]);
            *reinterpret_cast<float2*>(&sm[(r + 8) * EPI_STRIDE + colL]) =
                make_float2(acc[mt][nt][2], acc[mt][nt][3]);
        }
    }
    __syncthreads();

    const int n63 = tid & 63;
    const int mg  = tid >> 6;              // 0..7
    const int n   = cb * 64 + n63;
    const float bi_ = __ldg(&b0[n]);
    const float bf_ = __ldg(&b1[n]);
    const float bg_ = __ldg(&b2[n]);
    const float bc_ = __ldg(&b3[n]);
    #pragma unroll 4
    for (int j = 0; j < 16; j++) {
        const int ml = mg * 16 + j;
        const int gm = m0 + ml;
        const float p0 = sm[ml * EPI_STRIDE + n63]       + bi_;
        const float p1 = sm[ml * EPI_STRIDE + 64 + n63]  + bf_;
        const float p2 = sm[ml * EPI_STRIDE + 128 + n63] + bg_;
        const float p3 = sm[ml * EPI_STRIDE + 192 + n63] + bc_;
        const float po = prevoutput[(size_t)gm * 2048 + n];
        const float gi = sigf(p0), gf = sigf(p1), gg = sigf(p2);
        const float gc = tanhf(p3);
        const float c  = gf * po + gi * gc;
        const float st = gg * tanhf(c);
        const size_t idx = (size_t)gm * 2048 + n;
        if (mode == 0) {
            out[idx] = c;
        } else if (mode == 1) {
            out[idx] = st; out[NELEM + idx] = c;
        } else {
            out[idx] = c; out[NELEM + idx] = st; out[2 * NELEM + idx] = c;
        }
    }
}

// ---------------------------------------------------------------------------
extern "C" void kernel_launch(void* const* d_in, const int* in_sizes, int n_in,
                              void* d_out, int out_size)
{
    const float* X      = (const float*)d_in[0];
    const float* states = (const float*)d_in[1];
    const float* S0 = states;
    const float* S1 = states + NELEM;

    static bool init_done = false;
    if (!init_done) {
        cudaFuncSetAttribute(gemm_fused,
                             cudaFuncAttributeMaxDynamicSharedMemorySize, SMEM_BYTES);
        init_done = true;
    }

    WPtrs wp;
    wp.p[0] = (const float*)d_in[2];   // Wi
    wp.p[1] = (const float*)d_in[5];   // Wf
    wp.p[2] = (const float*)d_in[8];   // Wg
    wp.p[3] = (const float*)d_in[11];  // Wc
    wp.p[4] = (const float*)d_in[3];   // Ui
    wp.p[5] = (const float*)d_in[6];   // Uf
    wp.p[6] = (const float*)d_in[9];   // Ug
    wp.p[7] = (const float*)d_in[12];  // Uc
    const float* b0 = (const float*)d_in[4];
    const float* b1 = (const float*)d_in[7];
    const float* b2 = (const float*)d_in[10];
    const float* b3 = (const float*)d_in[13];

    int mode;
    if (out_size == NELEM)          mode = 0;
    else if (out_size == 2 * NELEM) mode = 1;
    else                            mode = 2;

    convert_A<<<256, 256>>>(X, S0);        // 512*4096 halfs / 32 per thread
    convert_B<<<4096, 256>>>(wp);          // 4096*8192 halfs / 32 per thread

    dim3 grid(BQ / BM, 32);   // 128 CTAs
    gemm_fused<<<grid, NTHREADS, SMEM_BYTES>>>(b0, b1, b2, b3, S1, (float*)d_out, mode);
}

// round 14
// speedup vs baseline: 1.3113x; 1.1158x over previous
#include <cuda_runtime.h>
#include <cuda_fp16.h>
#include <cstdint>
#include <math.h>

#define BQ 512
#define II 2048
#define HH 2048
#define NELEM (BQ * HH)

#define BM 128
#define BN 256            // smem B cols = 64 real n x 4 gates
#define BK 64
#define STAGES 3
#define NITER 64          // full K = 4096
#define NTHREADS 512

#define A_LDS 72
#define B_LDS 264
#define A_STAGE_B (BM * A_LDS * 2)     // 18432
#define B_STAGE_B (BK * B_LDS * 2)     // 33792
#define STAGE_B   (A_STAGE_B + B_STAGE_B)
#define SMEM_BYTES (STAGES * STAGE_B)  // 156672
#define EPI_STRIDE 264                 // fp32 staging stride (128*264*4 = 135KB)

// B_h: [4096 k][8192 C] fp16, C = nblk*256 + gate*64 + n63  (n = nblk*64 + n63)
__device__ __half A_h[(size_t)BQ * 4096];              // 4 MB
__device__ __half B_h[(size_t)4096 * 8192];            // 64 MB

// ---------------------------------------------------------------------------
__device__ __forceinline__ uint32_t smem_u32(const void* p) {
    uint32_t a;
    asm("{ .reg .u64 t; cvta.to.shared.u64 t, %1; cvt.u32.u64 %0, t; }" : "=r"(a) : "l"(p));
    return a;
}
__device__ __forceinline__ void cpasync16(uint32_t dst, const void* src) {
    asm volatile("cp.async.cg.shared.global [%0], [%1], 16;" :: "r"(dst), "l"(src));
}
#define CP_COMMIT() asm volatile("cp.async.commit_group;" ::: "memory")
#define CP_WAIT(n)  asm volatile("cp.async.wait_group %0;" :: "n"(n) : "memory")

__device__ __forceinline__ uint32_t packh2(float lo, float hi) {
    uint32_t r; asm("cvt.rn.f16x2.f32 %0, %1, %2;" : "=r"(r) : "f"(hi), "f"(lo)); return r;
}
// evict-first 16B load (weights are dead after conversion)
__device__ __forceinline__ float4 ldcs4(const float4* p) {
    float4 v;
    asm volatile("ld.global.cs.v4.f32 {%0,%1,%2,%3}, [%4];"
                 : "=f"(v.x), "=f"(v.y), "=f"(v.z), "=f"(v.w) : "l"(p));
    return v;
}
__device__ __forceinline__ void ldsm_x4(uint32_t* r, uint32_t addr) {
    asm volatile("ldmatrix.sync.aligned.m8n8.x4.shared.b16 {%0,%1,%2,%3}, [%4];"
                 : "=r"(r[0]), "=r"(r[1]), "=r"(r[2]), "=r"(r[3]) : "r"(addr));
}
__device__ __forceinline__ void ldsm_x4_t(uint32_t* r, uint32_t addr) {
    asm volatile("ldmatrix.sync.aligned.m8n8.x4.trans.shared.b16 {%0,%1,%2,%3}, [%4];"
                 : "=r"(r[0]), "=r"(r[1]), "=r"(r[2]), "=r"(r[3]) : "r"(addr));
}
__device__ __forceinline__ void mma16n8k16(float* c, const uint32_t* a,
                                           uint32_t b0, uint32_t b1) {
    asm volatile(
        "mma.sync.aligned.m16n8k16.row.col.f32.f16.f16.f32 "
        "{%0,%1,%2,%3}, {%4,%5,%6,%7}, {%8,%9}, {%0,%1,%2,%3};"
        : "+f"(c[0]), "+f"(c[1]), "+f"(c[2]), "+f"(c[3])
        : "r"(a[0]), "r"(a[1]), "r"(a[2]), "r"(a[3]), "r"(b0), "r"(b1));
}
__device__ __forceinline__ float sigf(float x) { return 1.0f / (1.0f + __expf(-x)); }

// ---------------------------------------------------------------------------
// fp32 -> fp16 converts — occupancy x MLP balanced
// ---------------------------------------------------------------------------
struct WPtrs { const float* p[8]; };   // Wi,Wf,Wg,Wc, Ui,Uf,Ug,Uc

// 8192 blocks x 256 thr, 16 halfs/thread (MLP = 4 x 16B loads).
// 16-half span stays inside one (k, gate) block (C0 16-aligned, gate width 64).
__global__ __launch_bounds__(256) void convert_B(WPtrs wp) {
    const uint32_t gid = blockIdx.x * 256 + threadIdx.x;
    const size_t el0 = (size_t)gid * 16;              // half index
    const int k  = (int)(el0 >> 13);
    const int C0 = (int)(el0 & 8191);
    const int gate = (C0 >> 6) & 3;
    const int n = ((C0 >> 8) << 6) | (C0 & 63);
    const float* base = (k < 2048)
        ? wp.p[gate]     + ((size_t)k << 11) + n
        : wp.p[4 + gate] + ((size_t)(k - 2048) << 11) + n;

    float4 v[4];
    #pragma unroll
    for (int j = 0; j < 4; j++)
        v[j] = ldcs4(reinterpret_cast<const float4*>(base) + j);

    uint2* dst = reinterpret_cast<uint2*>(B_h) + (size_t)gid * 4;
    #pragma unroll
    for (int j = 0; j < 4; j++) {
        uint2 o;
        o.x = packh2(v[j].x, v[j].y);
        o.y = packh2(v[j].z, v[j].w);
        dst[j] = o;
    }
}

// 1024 blocks x 256 thr, 8 halfs/thread (MLP = 2).
__global__ __launch_bounds__(256) void convert_A(const float* __restrict__ X,
                                                 const float* __restrict__ S0) {
    const uint32_t gid = blockIdx.x * 256 + threadIdx.x;
    const size_t el0 = (size_t)gid * 8;
    const int m  = (int)(el0 >> 12);
    const int k0 = (int)(el0 & 4095);
    const float* base = (k0 < 2048) ? X  + ((size_t)m << 11) + k0
                                    : S0 + ((size_t)m << 11) + (k0 - 2048);
    float4 v[2];
    #pragma unroll
    for (int j = 0; j < 2; j++)
        v[j] = reinterpret_cast<const float4*>(base)[j];

    uint2* dst = reinterpret_cast<uint2*>(A_h) + (size_t)gid * 2;
    #pragma unroll
    for (int j = 0; j < 2; j++) {
        uint2 o;
        o.x = packh2(v[j].x, v[j].y);
        o.y = packh2(v[j].z, v[j].w);
        dst[j] = o;
    }
}

// ---------------------------------------------------------------------------
// Full-K fused GEMM + LSTM elementwise. 512 threads, 16 warps.
// Warp grid 4(M) x 4(N): warp tile 32x64 (each N-quad = one gate).
// grid (4 Mtiles, 32 col-blocks) = 128 CTAs.
// ---------------------------------------------------------------------------
__global__ __launch_bounds__(NTHREADS, 1) void gemm_fused(
    const float* __restrict__ b0, const float* __restrict__ b1,
    const float* __restrict__ b2, const float* __restrict__ b3,
    const float* __restrict__ prevoutput, float* __restrict__ out, int mode)
{
    extern __shared__ char smem[];
    const uint32_t sbase = smem_u32(smem);

    const int tid  = threadIdx.x;
    const int lane = tid & 31;
    const int warp = tid >> 5;
    const int wm   = (warp & 3) * 32;      // warp M offset
    const int wn   = (warp >> 2) * 64;     // warp N offset (gate = warp>>2)

    const int m0 = blockIdx.x * BM;
    const int cb = blockIdx.y;             // real n base = cb*64

    float acc[2][8][4];
    #pragma unroll
    for (int mt = 0; mt < 2; mt++)
        #pragma unroll
        for (int nt = 0; nt < 8; nt++)
            #pragma unroll
            for (int q = 0; q < 4; q++) acc[mt][nt][q] = 0.0f;

    auto load_chunk = [&](int i, int s) {
        const int kb = i * BK;
        const uint32_t aofs = sbase + (uint32_t)s * STAGE_B;
        const uint32_t bofs = aofs + A_STAGE_B;
        #pragma unroll
        for (int j = 0; j < 2; j++) {             // A: 1024 16B-chunks
            const int c   = tid + NTHREADS * j;
            const int row = c >> 3, cin = c & 7;
            cpasync16(aofs + (uint32_t)(row * A_LDS + cin * 8) * 2,
                      A_h + ((size_t)(m0 + row) << 12) + kb + cin * 8);
        }
        #pragma unroll
        for (int j = 0; j < 4; j++) {             // B: 2048 16B-chunks
            const int c   = tid + NTHREADS * j;
            const int row = c >> 5, cin = c & 31;
            cpasync16(bofs + (uint32_t)(row * B_LDS + cin * 8) * 2,
                      B_h + ((size_t)(kb + row) << 13) + cb * 256 + cin * 8);
        }
    };

    #pragma unroll
    for (int s = 0; s < STAGES - 1; s++) { load_chunk(s, s); CP_COMMIT(); }

    const int lr = lane & 15;
    const int lh = lane >> 4;

    for (int i = 0; i < NITER; i++) {
        CP_WAIT(STAGES - 2);
        __syncthreads();

        if (i + STAGES - 1 < NITER)
            load_chunk(i + STAGES - 1, (i + STAGES - 1) % STAGES);
        CP_COMMIT();

        const int s = i % STAGES;
        const uint32_t aofs = sbase + (uint32_t)s * STAGE_B;
        const uint32_t bofs = aofs + A_STAGE_B;

        #pragma unroll
        for (int ks = 0; ks < 4; ks++) {
            const int k = ks * 16;
            uint32_t a[2][4], b[4][4];
            #pragma unroll
            for (int mt = 0; mt < 2; mt++)
                ldsm_x4(a[mt], aofs +
                        (uint32_t)((wm + mt * 16 + lr) * A_LDS + k + lh * 8) * 2);
            #pragma unroll
            for (int p = 0; p < 4; p++)
                ldsm_x4_t(b[p], bofs +
                          (uint32_t)((k + lr) * B_LDS + wn + p * 16 + lh * 8) * 2);
            #pragma unroll
            for (int mt = 0; mt < 2; mt++)
                #pragma unroll
                for (int p = 0; p < 4; p++) {
                    mma16n8k16(acc[mt][2 * p + 0], a[mt], b[p][0], b[p][1]);
                    mma16n8k16(acc[mt][2 * p + 1], a[mt], b[p][2], b[p][3]);
                }
        }
        __syncthreads();
    }

    // ---- epilogue: stage acc to smem, then fused LSTM elementwise ----
    CP_WAIT(0);
    __syncthreads();
    float* sm = reinterpret_cast<float*>(smem);   // [128][EPI_STRIDE]
    #pragma unroll
    for (int mt = 0; mt < 2; mt++) {
        const int r = wm + mt * 16 + (lane >> 2);
        #pragma unroll
        for (int nt = 0; nt < 8; nt++) {
            const int colL = wn + nt * 8 + (lane & 3) * 2;
            *reinterpret_cast<float2*>(&sm[r * EPI_STRIDE + colL]) =
                make_float2(acc[mt][nt][0], acc[mt][nt][1]);
            *reinterpret_cast<float2*>(&sm[(r + 8) * EPI_STRIDE + colL]) =
                make_float2(acc[mt][nt][2], acc[mt][nt][3]);
        }
    }
    __syncthreads();

    const int n63 = tid & 63;
    const int mg  = tid >> 6;              // 0..7
    const int n   = cb * 64 + n63;
    const float bi_ = __ldg(&b0[n]);
    const float bf_ = __ldg(&b1[n]);
    const float bg_ = __ldg(&b2[n]);
    const float bc_ = __ldg(&b3[n]);
    #pragma unroll 4
    for (int j = 0; j < 16; j++) {
        const int ml = mg * 16 + j;
        const int gm = m0 + ml;
        const float p0 = sm[ml * EPI_STRIDE + n63]       + bi_;
        const float p1 = sm[ml * EPI_STRIDE + 64 + n63]  + bf_;
        const float p2 = sm[ml * EPI_STRIDE + 128 + n63] + bg_;
        const float p3 = sm[ml * EPI_STRIDE + 192 + n63] + bc_;
        const float po = prevoutput[(size_t)gm * 2048 + n];
        const float gi = sigf(p0), gf = sigf(p1), gg = sigf(p2);
        const float gc = tanhf(p3);
        const float c  = gf * po + gi * gc;
        const float st = gg * tanhf(c);
        const size_t idx = (size_t)gm * 2048 + n;
        if (mode == 0) {
            out[idx] = c;
        } else if (mode == 1) {
            out[idx] = st; out[NELEM + idx] = c;
        } else {
            out[idx] = c; out[NELEM + idx] = st; out[2 * NELEM + idx] = c;
        }
    }
}

// ---------------------------------------------------------------------------
extern "C" void kernel_launch(void* const* d_in, const int* in_sizes, int n_in,
                              void* d_out, int out_size)
{
    const float* X      = (const float*)d_in[0];
    const float* states = (const float*)d_in[1];
    const float* S0 = states;
    const float* S1 = states + NELEM;

    static bool init_done = false;
    if (!init_done) {
        cudaFuncSetAttribute(gemm_fused,
                             cudaFuncAttributeMaxDynamicSharedMemorySize, SMEM_BYTES);
        init_done = true;
    }

    WPtrs wp;
    wp.p[0] = (const float*)d_in[2];   // Wi
    wp.p[1] = (const float*)d_in[5];   // Wf
    wp.p[2] = (const float*)d_in[8];   // Wg
    wp.p[3] = (const float*)d_in[11];  // Wc
    wp.p[4] = (const float*)d_in[3];   // Ui
    wp.p[5] = (const float*)d_in[6];   // Uf
    wp.p[6] = (const float*)d_in[9];   // Ug
    wp.p[7] = (const float*)d_in[12];  // Uc
    const float* b0 = (const float*)d_in[4];
    const float* b1 = (const float*)d_in[7];
    const float* b2 = (const float*)d_in[10];
    const float* b3 = (const float*)d_in[13];

    int mode;
    if (out_size == NELEM)          mode = 0;
    else if (out_size == 2 * NELEM) mode = 1;
    else                            mode = 2;

    convert_A<<<1024, 256>>>(X, S0);       // 512*4096 halfs / 8 per thread
    convert_B<<<8192, 256>>>(wp);          // 4096*8192 halfs / 16 per thread

    dim3 grid(BQ / BM, 32);   // 128 CTAs
    gemm_fused<<<grid, NTHREADS, SMEM_BYTES>>>(b0, b1, b2, b3, S1, (float*)d_out, mode);
}